// round 16
// baseline (speedup 1.0000x reference)
#include <cuda_runtime.h>
#include <cstdint>

// DynamicGRU: B=32, T=2048, D=256, N=256
// Phase 1: PRE = x @ [W_g[:256,:] | W_c[:256,:]] + bias — tf32 mma.sync GEMM,
//          register-staged double buffering (LDG of tile k+1 overlaps MAC k).
// Phase 2: persistent scan, 4-CTA cluster per batch row, register-resident
//          weights, st.async + tx-mbarrier exchange with b64-packed messages.

#define BATCH_ 32
#define T_     2048

__device__ float g_pre[(size_t)BATCH_ * T_ * 768];

// ---------------------------------------------------------------------------
// Phase 1 helpers
// ---------------------------------------------------------------------------
__device__ __forceinline__ float tf32_(float x) {
    float r;
    asm("cvt.rna.tf32.f32 %0, %1;" : "=f"(r) : "f"(x));
    return r;
}
__device__ __forceinline__ void mma_tf32_(float* d, const uint32_t* a, const uint32_t* b) {
    asm volatile(
        "mma.sync.aligned.m16n8k8.row.col.f32.tf32.tf32.f32 "
        "{%0,%1,%2,%3}, {%4,%5,%6,%7}, {%8,%9}, {%0,%1,%2,%3};"
        : "+f"(d[0]), "+f"(d[1]), "+f"(d[2]), "+f"(d[3])
        : "r"(a[0]), "r"(a[1]), "r"(a[2]), "r"(a[3]), "r"(b[0]), "r"(b[1]));
}

// ---------------------------------------------------------------------------
// Phase 1: tf32 GEMM  [65536,256] x [256,768] -> g_pre (bias folded).
// BM=128, BN=64, BK=32, 256 threads, double-buffered through registers.
// ---------------------------------------------------------------------------
__global__ __launch_bounds__(256) void gemm_pre_tf32_kernel(
    const float* __restrict__ x,
    const float* __restrict__ Wg, const float* __restrict__ bg,
    const float* __restrict__ Wc, const float* __restrict__ bc)
{
    __shared__ __align__(16) float As[128][36];
    __shared__ __align__(16) float Bs[32][72];

    const int bn  = blockIdx.x;
    const int bm  = blockIdx.y;
    const int tid = threadIdx.x;
    const int ww  = tid >> 5;
    const int lane = tid & 31;
    const int wm  = ww >> 2;
    const int wn  = ww & 3;
    const int lr  = lane >> 2;
    const int lq  = lane & 3;

    const float* Wp; int ldw, coff; const float* bias;
    if (bn < 8) { Wp = Wg; ldw = 512; coff = bn * 64;        bias = bg + coff; }
    else        { Wp = Wc; ldw = 256; coff = (bn - 8) * 64;  bias = bc + coff; }

    const float* Ag = x + (size_t)(bm * 128) * 256;

    const int arow = tid >> 1;
    const int akq  = (tid & 1) * 16;
    const int brow = tid >> 3;
    const int bnq  = (tid & 7) * 8;

    float acc[4][2][4];
#pragma unroll
    for (int mt = 0; mt < 4; ++mt)
#pragma unroll
        for (int nt = 0; nt < 2; ++nt)
#pragma unroll
            for (int i = 0; i < 4; ++i) acc[mt][nt][i] = 0.f;

    // preload tile 0 into registers
    float4 ra[4], rb[2];
#pragma unroll
    for (int j = 0; j < 4; ++j)
        ra[j] = *(const float4*)(Ag + (size_t)arow * 256 + akq + j * 4);
#pragma unroll
    for (int j = 0; j < 2; ++j)
        rb[j] = *(const float4*)(Wp + (size_t)brow * ldw + coff + bnq + j * 4);

    for (int kt = 0; kt < 8; ++kt) {
        // store current tile to smem with tf32 rounding
#pragma unroll
        for (int j = 0; j < 4; ++j) {
            As[arow][akq + j * 4 + 0] = tf32_(ra[j].x);
            As[arow][akq + j * 4 + 1] = tf32_(ra[j].y);
            As[arow][akq + j * 4 + 2] = tf32_(ra[j].z);
            As[arow][akq + j * 4 + 3] = tf32_(ra[j].w);
        }
#pragma unroll
        for (int j = 0; j < 2; ++j) {
            Bs[brow][bnq + j * 4 + 0] = tf32_(rb[j].x);
            Bs[brow][bnq + j * 4 + 1] = tf32_(rb[j].y);
            Bs[brow][bnq + j * 4 + 2] = tf32_(rb[j].z);
            Bs[brow][bnq + j * 4 + 3] = tf32_(rb[j].w);
        }
        __syncthreads();

        // prefetch next tile (overlaps the MAC phase below)
        if (kt < 7) {
            const int kn = (kt + 1) * 32;
#pragma unroll
            for (int j = 0; j < 4; ++j)
                ra[j] = *(const float4*)(Ag + (size_t)arow * 256 + kn + akq + j * 4);
#pragma unroll
            for (int j = 0; j < 2; ++j)
                rb[j] = *(const float4*)(Wp + (size_t)(kn + brow) * ldw + coff + bnq + j * 4);
        }

#pragma unroll
        for (int ks = 0; ks < 4; ++ks) {
            const int k0 = ks * 8 + lq;
            uint32_t af[4][4];
#pragma unroll
            for (int mt = 0; mt < 4; ++mt) {
                const int r0 = wm * 64 + mt * 16 + lr;
                af[mt][0] = __float_as_uint(As[r0][k0]);
                af[mt][1] = __float_as_uint(As[r0 + 8][k0]);
                af[mt][2] = __float_as_uint(As[r0][k0 + 4]);
                af[mt][3] = __float_as_uint(As[r0 + 8][k0 + 4]);
            }
            uint32_t bf[2][2];
#pragma unroll
            for (int nt = 0; nt < 2; ++nt) {
                const int c0 = wn * 16 + nt * 8 + lr;
                bf[nt][0] = __float_as_uint(Bs[k0][c0]);
                bf[nt][1] = __float_as_uint(Bs[k0 + 4][c0]);
            }
#pragma unroll
            for (int mt = 0; mt < 4; ++mt)
#pragma unroll
                for (int nt = 0; nt < 2; ++nt)
                    mma_tf32_(acc[mt][nt], af[mt], bf[nt]);
        }
        __syncthreads();
    }

    float* Og = g_pre + (size_t)(bm * 128) * 768 + bn * 64;
#pragma unroll
    for (int mt = 0; mt < 4; ++mt) {
#pragma unroll
        for (int nt = 0; nt < 2; ++nt) {
            const int row = wm * 64 + mt * 16 + lr;
            const int cl  = wn * 16 + nt * 8 + 2 * lq;
            float b0 = bias[cl], b1 = bias[cl + 1];
            float* d0 = Og + (size_t)row * 768 + cl;
            float* d1 = Og + (size_t)(row + 8) * 768 + cl;
            d0[0] = acc[mt][nt][0] + b0;
            d0[1] = acc[mt][nt][1] + b1;
            d1[0] = acc[mt][nt][2] + b0;
            d1[1] = acc[mt][nt][3] + b1;
        }
    }
}

// ---------------------------------------------------------------------------
// Phase 2 helpers
// ---------------------------------------------------------------------------
__device__ __forceinline__ void cluster_sync_() {
    asm volatile("barrier.cluster.arrive.aligned;" ::: "memory");
    asm volatile("barrier.cluster.wait.aligned;" ::: "memory");
}
__device__ __forceinline__ uint32_t smem_u32_(const void* p) {
    uint32_t a;
    asm("{ .reg .u64 t; cvta.to.shared.u64 t, %1; cvt.u32.u64 %0, t; }"
        : "=r"(a) : "l"(p));
    return a;
}
__device__ __forceinline__ uint32_t mapa_(uint32_t laddr, int rk) {
    uint32_t ra;
    asm("mapa.shared::cluster.u32 %0, %1, %2;" : "=r"(ra) : "r"(laddr), "r"(rk));
    return ra;
}
__device__ __forceinline__ void mbar_init_(uint32_t laddr, uint32_t cnt) {
    asm volatile("mbarrier.init.shared.b64 [%0], %1;" :: "r"(laddr), "r"(cnt) : "memory");
}
__device__ __forceinline__ void mbar_expect_tx_(uint32_t laddr, uint32_t bytes) {
    asm volatile("mbarrier.arrive.expect_tx.shared.b64 _, [%0], %1;"
                 :: "r"(laddr), "r"(bytes) : "memory");
}
__device__ __forceinline__ void st_async_b64_(uint32_t raddr, uint64_t v, uint32_t rmbar) {
    asm volatile("st.async.shared::cluster.mbarrier::complete_tx::bytes.b64 [%0], %1, [%2];"
                 :: "r"(raddr), "l"(v), "r"(rmbar) : "memory");
}
__device__ __forceinline__ void mbar_wait_par_(uint32_t laddr, uint32_t parity) {
    asm volatile(
        "{\n\t.reg .pred P;\n\t"
        "WL%=:\n\t"
        "mbarrier.try_wait.parity.acquire.cta.shared::cta.b64 P, [%0], %1, 0x989680;\n\t"
        "@P bra.uni WD%=;\n\t"
        "bra.uni WL%=;\n\t"
        "WD%=:\n\t}"
        :: "r"(laddr), "r"(parity) : "memory");
}
__device__ __forceinline__ uint64_t pack2_(float a, float b) {
    uint64_t r;
    asm("mov.b64 %0, {%1, %2};" : "=l"(r) : "f"(a), "f"(b));
    return r;
}
__device__ __forceinline__ void unpack2_(uint64_t v, float& a, float& b) {
    asm("mov.b64 {%0, %1}, %2;" : "=f"(a), "=f"(b) : "l"(v));
}
__device__ __forceinline__ void fma2_(uint64_t& d, uint64_t a, uint64_t b) {
    asm("fma.rn.f32x2 %0, %1, %2, %0;" : "+l"(d) : "l"(a), "l"(b));
}
__device__ __forceinline__ void lds_v2u64_(uint32_t addr, uint64_t& a, uint64_t& b) {
    asm volatile("ld.shared.v2.u64 {%0, %1}, [%2];" : "=l"(a), "=l"(b) : "r"(addr));
}
__device__ __forceinline__ float fast_sigmoid_(float s) {
    return __fdividef(1.f, 1.f + __expf(-s));
}
__device__ __forceinline__ float fast_tanh_(float s) {
    return 1.f - __fdividef(2.f, __expf(2.f * s) + 1.f);
}

// ---------------------------------------------------------------------------
// Phase 2: grid = 128 CTAs, cluster(4,1,1), 512 threads (R15 structure,
// b64-packed st.async: even lanes of tid<64 send column pairs).
// ---------------------------------------------------------------------------
__global__ void __cluster_dims__(4, 1, 1) __launch_bounds__(512, 1)
gru_rec_kernel(const float* __restrict__ Wg, const float* __restrict__ Wc,
               const float* __restrict__ h0, float* __restrict__ out)
{
    __shared__ __align__(16) float hbuf[256];
    __shared__ __align__(16) float rhbuf[256];
    __shared__ float ubuf[64];
    __shared__ float pbuf[2 * 192];
    __shared__ __align__(16) float redA[128 * 4];
    __shared__ __align__(16) float redB[64 * 8];
    __shared__ __align__(8) uint64_t mbar_rh;
    __shared__ __align__(8) uint64_t mbar_h;

    const int tid  = threadIdx.x;
    const int w    = tid >> 5;
    const int lane = tid & 31;
    uint32_t rank;
    asm("mov.u32 %0, %%cluster_ctarank;" : "=r"(rank));
    const int b = blockIdx.x >> 2;

    const int sg  = w & 3;
    const int col = (w >> 2) * 32 + lane;
    const int gcol = (col < 64) ? (int)(rank * 64 + col)
                                : (int)(256 + rank * 64 + (col - 64));
    const int sc  = w & 7;
    const int cc  = (w >> 3) * 32 + lane;
    const int ccol = rank * 64 + cc;

    uint64_t wg2[32];
#pragma unroll
    for (int j = 0; j < 16; ++j) {
        int k = sg * 64 + j * 4;
        float w0 = Wg[(size_t)(256 + k + 0) * 512 + gcol];
        float w1 = Wg[(size_t)(256 + k + 1) * 512 + gcol];
        float w2 = Wg[(size_t)(256 + k + 2) * 512 + gcol];
        float w3 = Wg[(size_t)(256 + k + 3) * 512 + gcol];
        wg2[2 * j]     = pack2_(w0, w1);
        wg2[2 * j + 1] = pack2_(w2, w3);
    }
    uint64_t wc2[16];
#pragma unroll
    for (int j = 0; j < 8; ++j) {
        int k = sc * 32 + j * 4;
        float w0 = Wc[(size_t)(256 + k + 0) * 256 + ccol];
        float w1 = Wc[(size_t)(256 + k + 1) * 256 + ccol];
        float w2 = Wc[(size_t)(256 + k + 2) * 256 + ccol];
        float w3 = Wc[(size_t)(256 + k + 3) * 256 + ccol];
        wc2[2 * j]     = pack2_(w0, w1);
        wc2[2 * j + 1] = pack2_(w2, w3);
    }

    for (int i = tid; i < 256; i += 512) hbuf[i] = h0[b * 256 + i];

    const uint32_t mrh_l = smem_u32_(&mbar_rh);
    const uint32_t mh_l  = smem_u32_(&mbar_h);
    if (tid == 0) {
        mbar_init_(mrh_l, 1);
        mbar_init_(mh_l, 1);
        mbar_expect_tx_(mrh_l, 1024);
    }

    int preidx = 0;
    if      (tid < 64)  preidx = rank * 64 + tid;
    else if (tid < 128) preidx = 256 + rank * 64 + (tid - 64);
    else if (tid < 192) preidx = 512 + rank * 64 + (tid - 128);

    const float* prow = g_pre + (size_t)b * T_ * 768;
    float*       orow = out   + (size_t)b * T_ * 256;

    if (tid < 192) pbuf[tid] = prow[preidx];
    __syncthreads();
    cluster_sync_();

    const uint32_t hb   = smem_u32_(hbuf);
    const uint32_t rhb  = smem_u32_(rhbuf);
    const uint32_t ha_g = hb  + sg * 256;
    const uint32_t ra_c = rhb + sc * 128;

    // pair-base remote addresses for even lanes (element index = tid&62)
    uint32_t rh_rem[4], h_rem[4];
    {
        uint32_t e = (rank * 64 + (tid & 62)) * 4;
#pragma unroll
        for (int rk = 0; rk < 4; ++rk) {
            rh_rem[rk] = mapa_(rhb + e, rk);
            h_rem[rk]  = mapa_(hb + e,  rk);
        }
    }
    const uint32_t d_rh2m = mrh_l - (rhb + (rank * 64 + (tid & 62)) * 4);
    const uint32_t d_h2m  = mh_l  - (hb  + (rank * 64 + (tid & 62)) * 4);

    for (int t = 0; t < T_; ++t) {
        const int cur = (t & 1) * 192, nxt = ((t & 1) ^ 1) * 192;
        const uint32_t par = (uint32_t)(t & 1);

        if (tid == 0) mbar_expect_tx_(mh_l, 1024);

        float pre_next = 0.f;
        if (tid < 192 && t + 1 < T_)
            pre_next = prow[(size_t)(t + 1) * 768 + preidx];

        // ---- gates partial: h[sg*64..+64) . wg ----
        {
            uint64_t a0 = 0, a1 = 0;
#pragma unroll
            for (int j = 0; j < 16; ++j) {
                uint64_t h01, h23;
                lds_v2u64_(ha_g + j * 16, h01, h23);
                fma2_(a0, wg2[2 * j],     h01);
                fma2_(a1, wg2[2 * j + 1], h23);
            }
            float x0, x1, y0, y1;
            unpack2_(a0, x0, x1);
            unpack2_(a1, y0, y1);
            redA[col * 4 + sg] = (x0 + x1) + (y0 + y1);
        }
        __syncthreads();

        // ---- gate finalize ----
        if (tid < 128) {
            float4 p4 = *(const float4*)&redA[tid * 4];
            float s = p4.x + p4.y + p4.z + p4.w + pbuf[cur + tid];
            float g = fast_sigmoid_(s);
            if (tid < 64) {
                float rh = g * hbuf[rank * 64 + tid];
                float rh_o = __shfl_xor_sync(0xffffffffu, rh, 1);
                if ((tid & 1) == 0) {
                    uint64_t v = pack2_(rh, rh_o);
#pragma unroll
                    for (int rk = 0; rk < 4; ++rk)
                        st_async_b64_(rh_rem[rk], v, rh_rem[rk] + d_rh2m);
                }
            } else {
                ubuf[tid - 64] = g;
            }
        }
        mbar_wait_par_(mrh_l, par);
        if (tid == 0) mbar_expect_tx_(mrh_l, 1024);

        // ---- candidate partial: rh[sc*32..+32) . wc ----
        {
            uint64_t c0 = 0, c1 = 0;
#pragma unroll
            for (int j = 0; j < 8; ++j) {
                uint64_t h01, h23;
                lds_v2u64_(ra_c + j * 16, h01, h23);
                fma2_(c0, wc2[2 * j],     h01);
                fma2_(c1, wc2[2 * j + 1], h23);
            }
            float x0, x1, y0, y1;
            unpack2_(c0, x0, x1);
            unpack2_(c1, y0, y1);
            redB[cc * 8 + sc] = (x0 + x1) + (y0 + y1);
        }
        __syncthreads();

        // ---- h update ----
        if (tid < 64) {
            float4 p0 = *(const float4*)&redB[tid * 8];
            float4 p1 = *(const float4*)&redB[tid * 8 + 4];
            float s = ((p0.x + p0.y) + (p0.z + p0.w))
                    + ((p1.x + p1.y) + (p1.z + p1.w))
                    + pbuf[cur + 128 + tid];
            float c  = fast_tanh_(s);
            float u  = ubuf[tid];
            float hn = u * hbuf[rank * 64 + tid] + (1.f - u) * c;
            orow[(size_t)t * 256 + rank * 64 + tid] = hn;
            float hn_o = __shfl_xor_sync(0xffffffffu, hn, 1);
            if (t + 1 < T_ && (tid & 1) == 0) {
                uint64_t v = pack2_(hn, hn_o);
#pragma unroll
                for (int rk = 0; rk < 4; ++rk)
                    st_async_b64_(h_rem[rk], v, h_rem[rk] + d_h2m);
            }
        }
        if (tid < 192) pbuf[nxt + tid] = pre_next;
        if (t + 1 < T_) mbar_wait_par_(mh_l, par);
    }
}

// ---------------------------------------------------------------------------
extern "C" void kernel_launch(void* const* d_in, const int* in_sizes, int n_in,
                              void* d_out, int out_size) {
    const float* x  = (const float*)d_in[0];
    const float* h0 = (const float*)d_in[1];
    const float* Wg = (const float*)d_in[2];
    const float* bg = (const float*)d_in[3];
    const float* Wc = (const float*)d_in[4];
    const float* bc = (const float*)d_in[5];
    float* out = (float*)d_out;

    dim3 g1(12, 512);
    gemm_pre_tf32_kernel<<<g1, 256>>>(x, Wg, bg, Wc, bc);
    gru_rec_kernel<<<128, 512>>>(Wg, Wc, h0, out);
}

// round 17
// speedup vs baseline: 2.0240x; 2.0240x over previous
#include <cuda_runtime.h>
#include <cstdint>

// DynamicGRU: B=32, T=2048, D=256, N=256
// Phase 1: PRE = x @ [W_g[:256,:] | W_c[:256,:]] + bias — tf32 mma.sync GEMM (R13).
// Phase 2: persistent scan, 4-CTA cluster per batch row, register-resident
//          weights, st.async + tx-mbarrier exchange (R15 mechanism), with the
//          gate MAC split r/u: u-MAC runs in the rh-hop wait shadow.
//          hbuf double-buffered by step parity (orders u-MAC vs remote h).

#define BATCH_ 32
#define T_     2048

__device__ float g_pre[(size_t)BATCH_ * T_ * 768];

// ---------------------------------------------------------------------------
// Phase 1 helpers
// ---------------------------------------------------------------------------
__device__ __forceinline__ float tf32_(float x) {
    float r;
    asm("cvt.rna.tf32.f32 %0, %1;" : "=f"(r) : "f"(x));
    return r;
}
__device__ __forceinline__ void mma_tf32_(float* d, const uint32_t* a, const uint32_t* b) {
    asm volatile(
        "mma.sync.aligned.m16n8k8.row.col.f32.tf32.tf32.f32 "
        "{%0,%1,%2,%3}, {%4,%5,%6,%7}, {%8,%9}, {%0,%1,%2,%3};"
        : "+f"(d[0]), "+f"(d[1]), "+f"(d[2]), "+f"(d[3])
        : "r"(a[0]), "r"(a[1]), "r"(a[2]), "r"(a[3]), "r"(b[0]), "r"(b[1]));
}

// ---------------------------------------------------------------------------
// Phase 1: tf32 GEMM  [65536,256] x [256,768] -> g_pre (bias folded). (R13)
// ---------------------------------------------------------------------------
__global__ __launch_bounds__(256) void gemm_pre_tf32_kernel(
    const float* __restrict__ x,
    const float* __restrict__ Wg, const float* __restrict__ bg,
    const float* __restrict__ Wc, const float* __restrict__ bc)
{
    __shared__ __align__(16) float As[128][36];
    __shared__ __align__(16) float Bs[32][72];

    const int bn  = blockIdx.x;
    const int bm  = blockIdx.y;
    const int tid = threadIdx.x;
    const int ww  = tid >> 5;
    const int lane = tid & 31;
    const int wm  = ww >> 2;
    const int wn  = ww & 3;
    const int lr  = lane >> 2;
    const int lq  = lane & 3;

    const float* Wp; int ldw, coff; const float* bias;
    if (bn < 8) { Wp = Wg; ldw = 512; coff = bn * 64;        bias = bg + coff; }
    else        { Wp = Wc; ldw = 256; coff = (bn - 8) * 64;  bias = bc + coff; }

    const float* Ag = x + (size_t)(bm * 128) * 256;

    const int arow = tid >> 1;
    const int akq  = (tid & 1) * 16;
    const int brow = tid >> 3;
    const int bnq  = (tid & 7) * 8;

    float acc[4][2][4];
#pragma unroll
    for (int mt = 0; mt < 4; ++mt)
#pragma unroll
        for (int nt = 0; nt < 2; ++nt)
#pragma unroll
            for (int i = 0; i < 4; ++i) acc[mt][nt][i] = 0.f;

    for (int kt = 0; kt < 256; kt += 32) {
#pragma unroll
        for (int j = 0; j < 4; ++j) {
            float4 v = *(const float4*)(Ag + (size_t)arow * 256 + kt + akq + j * 4);
            As[arow][akq + j * 4 + 0] = tf32_(v.x);
            As[arow][akq + j * 4 + 1] = tf32_(v.y);
            As[arow][akq + j * 4 + 2] = tf32_(v.z);
            As[arow][akq + j * 4 + 3] = tf32_(v.w);
        }
#pragma unroll
        for (int j = 0; j < 2; ++j) {
            float4 v = *(const float4*)(Wp + (size_t)(kt + brow) * ldw + coff + bnq + j * 4);
            Bs[brow][bnq + j * 4 + 0] = tf32_(v.x);
            Bs[brow][bnq + j * 4 + 1] = tf32_(v.y);
            Bs[brow][bnq + j * 4 + 2] = tf32_(v.z);
            Bs[brow][bnq + j * 4 + 3] = tf32_(v.w);
        }
        __syncthreads();

#pragma unroll
        for (int ks = 0; ks < 4; ++ks) {
            const int k0 = ks * 8 + lq;
            uint32_t af[4][4];
#pragma unroll
            for (int mt = 0; mt < 4; ++mt) {
                const int r0 = wm * 64 + mt * 16 + lr;
                af[mt][0] = __float_as_uint(As[r0][k0]);
                af[mt][1] = __float_as_uint(As[r0 + 8][k0]);
                af[mt][2] = __float_as_uint(As[r0][k0 + 4]);
                af[mt][3] = __float_as_uint(As[r0 + 8][k0 + 4]);
            }
            uint32_t bf[2][2];
#pragma unroll
            for (int nt = 0; nt < 2; ++nt) {
                const int c0 = wn * 16 + nt * 8 + lr;
                bf[nt][0] = __float_as_uint(Bs[k0][c0]);
                bf[nt][1] = __float_as_uint(Bs[k0 + 4][c0]);
            }
#pragma unroll
            for (int mt = 0; mt < 4; ++mt)
#pragma unroll
                for (int nt = 0; nt < 2; ++nt)
                    mma_tf32_(acc[mt][nt], af[mt], bf[nt]);
        }
        __syncthreads();
    }

    float* Og = g_pre + (size_t)(bm * 128) * 768 + bn * 64;
#pragma unroll
    for (int mt = 0; mt < 4; ++mt) {
#pragma unroll
        for (int nt = 0; nt < 2; ++nt) {
            const int row = wm * 64 + mt * 16 + lr;
            const int cl  = wn * 16 + nt * 8 + 2 * lq;
            float b0 = bias[cl], b1 = bias[cl + 1];
            float* d0 = Og + (size_t)row * 768 + cl;
            float* d1 = Og + (size_t)(row + 8) * 768 + cl;
            d0[0] = acc[mt][nt][0] + b0;
            d0[1] = acc[mt][nt][1] + b1;
            d1[0] = acc[mt][nt][2] + b0;
            d1[1] = acc[mt][nt][3] + b1;
        }
    }
}

// ---------------------------------------------------------------------------
// Phase 2 helpers
// ---------------------------------------------------------------------------
__device__ __forceinline__ void cluster_sync_() {
    asm volatile("barrier.cluster.arrive.aligned;" ::: "memory");
    asm volatile("barrier.cluster.wait.aligned;" ::: "memory");
}
__device__ __forceinline__ uint32_t smem_u32_(const void* p) {
    uint32_t a;
    asm("{ .reg .u64 t; cvta.to.shared.u64 t, %1; cvt.u32.u64 %0, t; }"
        : "=r"(a) : "l"(p));
    return a;
}
__device__ __forceinline__ uint32_t mapa_(uint32_t laddr, int rk) {
    uint32_t ra;
    asm("mapa.shared::cluster.u32 %0, %1, %2;" : "=r"(ra) : "r"(laddr), "r"(rk));
    return ra;
}
__device__ __forceinline__ void mbar_init_(uint32_t laddr, uint32_t cnt) {
    asm volatile("mbarrier.init.shared.b64 [%0], %1;" :: "r"(laddr), "r"(cnt) : "memory");
}
__device__ __forceinline__ void mbar_expect_tx_(uint32_t laddr, uint32_t bytes) {
    asm volatile("mbarrier.arrive.expect_tx.shared.b64 _, [%0], %1;"
                 :: "r"(laddr), "r"(bytes) : "memory");
}
__device__ __forceinline__ void st_async_f32_(uint32_t raddr, float v, uint32_t rmbar) {
    asm volatile("st.async.shared::cluster.mbarrier::complete_tx::bytes.f32 [%0], %1, [%2];"
                 :: "r"(raddr), "f"(v), "r"(rmbar) : "memory");
}
__device__ __forceinline__ void mbar_wait_par_(uint32_t laddr, uint32_t parity) {
    asm volatile(
        "{\n\t.reg .pred P;\n\t"
        "WL%=:\n\t"
        "mbarrier.try_wait.parity.acquire.cta.shared::cta.b64 P, [%0], %1, 0x989680;\n\t"
        "@P bra.uni WD%=;\n\t"
        "bra.uni WL%=;\n\t"
        "WD%=:\n\t}"
        :: "r"(laddr), "r"(parity) : "memory");
}
__device__ __forceinline__ uint64_t pack2_(float a, float b) {
    uint64_t r;
    asm("mov.b64 %0, {%1, %2};" : "=l"(r) : "f"(a), "f"(b));
    return r;
}
__device__ __forceinline__ void unpack2_(uint64_t v, float& a, float& b) {
    asm("mov.b64 {%0, %1}, %2;" : "=f"(a), "=f"(b) : "l"(v));
}
__device__ __forceinline__ void fma2_(uint64_t& d, uint64_t a, uint64_t b) {
    asm("fma.rn.f32x2 %0, %1, %2, %0;" : "+l"(d) : "l"(a), "l"(b));
}
__device__ __forceinline__ void lds_v2u64_(uint32_t addr, uint64_t& a, uint64_t& b) {
    asm volatile("ld.shared.v2.u64 {%0, %1}, [%2];" : "=l"(a), "=l"(b) : "r"(addr));
}
__device__ __forceinline__ float fast_sigmoid_(float s) {
    return __fdividef(1.f, 1.f + __expf(-s));
}
__device__ __forceinline__ float fast_tanh_(float s) {
    return 1.f - __fdividef(2.f, __expf(2.f * s) + 1.f);
}

// ---------------------------------------------------------------------------
// Phase 2: grid = 128 CTAs, cluster(4,1,1), 512 threads, 16 warps.
// Warp w: k-slice s8 = w&7 (32 k values), local col lc = (w>>3)*32+lane (0..63).
// Weights per thread: wr2/wu2/wc2, 16 u64 each (96 regs).
// Step: rMAC -> sync -> r-finalize+send -> uMAC (hop shadow) -> wait rh ->
//       candMAC -> sync -> h-finalize (u from redU) + send -> wait h.
// hbuf[2] double-buffered by parity; rhbuf single (ordered by mbar chains).
// ---------------------------------------------------------------------------
__global__ void __cluster_dims__(4, 1, 1) __launch_bounds__(512, 1)
gru_rec_kernel(const float* __restrict__ Wg, const float* __restrict__ Wc,
               const float* __restrict__ h0, float* __restrict__ out)
{
    __shared__ __align__(16) float hbuf[2][256];
    __shared__ __align__(16) float rhbuf[256];
    __shared__ float pbuf[2 * 192];
    __shared__ __align__(16) float redR[64 * 8];
    __shared__ __align__(16) float redU[64 * 8];
    __shared__ __align__(16) float redB[64 * 8];
    __shared__ __align__(8) uint64_t mbar_rh;
    __shared__ __align__(8) uint64_t mbar_h;

    const int tid  = threadIdx.x;
    const int w    = tid >> 5;
    const int lane = tid & 31;
    uint32_t rank;
    asm("mov.u32 %0, %%cluster_ctarank;" : "=r"(rank));
    const int b = blockIdx.x >> 2;

    const int s8 = w & 7;                 // k-slice (32 values)
    const int lc = (w >> 3) * 32 + lane;  // local col 0..63
    const int rcol = rank * 64 + lc;      // global r / cand col
    const int ucol = 256 + rcol;          // global u col

    // register-resident weights: 16 u64 each (k-pairs)
    uint64_t wr2[16], wu2[16], wc2[16];
#pragma unroll
    for (int j = 0; j < 8; ++j) {
        int k = s8 * 32 + j * 4;
        float r0 = Wg[(size_t)(256 + k + 0) * 512 + rcol];
        float r1 = Wg[(size_t)(256 + k + 1) * 512 + rcol];
        float r2 = Wg[(size_t)(256 + k + 2) * 512 + rcol];
        float r3 = Wg[(size_t)(256 + k + 3) * 512 + rcol];
        wr2[2 * j]     = pack2_(r0, r1);
        wr2[2 * j + 1] = pack2_(r2, r3);
        float u0 = Wg[(size_t)(256 + k + 0) * 512 + ucol];
        float u1 = Wg[(size_t)(256 + k + 1) * 512 + ucol];
        float u2 = Wg[(size_t)(256 + k + 2) * 512 + ucol];
        float u3 = Wg[(size_t)(256 + k + 3) * 512 + ucol];
        wu2[2 * j]     = pack2_(u0, u1);
        wu2[2 * j + 1] = pack2_(u2, u3);
        float c0 = Wc[(size_t)(256 + k + 0) * 256 + rcol];
        float c1 = Wc[(size_t)(256 + k + 1) * 256 + rcol];
        float c2 = Wc[(size_t)(256 + k + 2) * 256 + rcol];
        float c3 = Wc[(size_t)(256 + k + 3) * 256 + rcol];
        wc2[2 * j]     = pack2_(c0, c1);
        wc2[2 * j + 1] = pack2_(c2, c3);
    }

    for (int i = tid; i < 256; i += 512) {
        hbuf[0][i] = h0[b * 256 + i];
        hbuf[1][i] = 0.f;
    }

    const uint32_t mrh_l = smem_u32_(&mbar_rh);
    const uint32_t mh_l  = smem_u32_(&mbar_h);
    if (tid == 0) {
        mbar_init_(mrh_l, 1);
        mbar_init_(mh_l, 1);
        mbar_expect_tx_(mrh_l, 1024);   // arm rh phase 0
    }

    int preidx = 0;
    if      (tid < 64)  preidx = rank * 64 + tid;                // r
    else if (tid < 128) preidx = 256 + rank * 64 + (tid - 64);   // u
    else if (tid < 192) preidx = 512 + rank * 64 + (tid - 128);  // c

    const float* prow = g_pre + (size_t)b * T_ * 768;
    float*       orow = out   + (size_t)b * T_ * 256;

    if (tid < 192) pbuf[tid] = prow[preidx];
    __syncthreads();
    cluster_sync_();   // mbar init + arming + hbuf[0] visible cluster-wide

    const uint32_t hb0 = smem_u32_(&hbuf[0][0]);
    const uint32_t rhb = smem_u32_(rhbuf);
    // per-warp MAC base addresses (k-slice offset = s8*32 floats = s8*128 B)
    const uint32_t ha[2] = { hb0 + s8 * 128, hb0 + 1024 + s8 * 128 };
    const uint32_t ra    = rhb + s8 * 128;

    // producer (tid<64) remote data addresses + mbar deltas
    const uint32_t e = (rank * 64 + (tid & 63)) * 4;
    uint32_t rh_rem[4], h_rem[2][4];
#pragma unroll
    for (int rk = 0; rk < 4; ++rk) {
        rh_rem[rk]   = mapa_(rhb + e, rk);
        h_rem[0][rk] = mapa_(hb0 + e, rk);
        h_rem[1][rk] = h_rem[0][rk] + 1024;
    }
    const uint32_t d_rh2m  = mrh_l - (rhb + e);
    const uint32_t d_h2m0  = mh_l  - (hb0 + e);          // parity-0 buffer
    const uint32_t d_h2m1  = d_h2m0 - 1024;              // parity-1 buffer

    for (int t = 0; t < T_; ++t) {
        const int par = t & 1, npar = par ^ 1;
        const int cur = par * 192, nxt = npar * 192;
        const uint32_t parity = (uint32_t)par;

        if (tid == 0) mbar_expect_tx_(mh_l, 1024);   // arm h phase t

        float pre_next = 0.f;
        if (tid < 192 && t + 1 < T_)
            pre_next = prow[(size_t)(t + 1) * 768 + preidx];

        // ---- r partial: h[par][s8*32..+32) . wr ----
        {
            uint64_t a0 = 0, a1 = 0;
#pragma unroll
            for (int j = 0; j < 8; ++j) {
                uint64_t h01, h23;
                lds_v2u64_(ha[par] + j * 16, h01, h23);
                fma2_(a0, wr2[2 * j],     h01);
                fma2_(a1, wr2[2 * j + 1], h23);
            }
            float x0, x1, y0, y1;
            unpack2_(a0, x0, x1);
            unpack2_(a1, y0, y1);
            redR[lc * 8 + s8] = (x0 + x1) + (y0 + y1);
        }
        __syncthreads();

        // ---- r finalize + rh broadcast (tid<64) ----
        if (tid < 64) {
            float4 p0 = *(const float4*)&redR[tid * 8];
            float4 p1 = *(const float4*)&redR[tid * 8 + 4];
            float s = ((p0.x + p0.y) + (p0.z + p0.w))
                    + ((p1.x + p1.y) + (p1.z + p1.w))
                    + pbuf[cur + tid];
            float r  = fast_sigmoid_(s);
            float rh = r * hbuf[par][rank * 64 + tid];
#pragma unroll
            for (int rk = 0; rk < 4; ++rk)
                st_async_f32_(rh_rem[rk], rh, rh_rem[rk] + d_rh2m);
        }

        // ---- u partial (local h only) — runs in the rh-hop shadow ----
        {
            uint64_t a0 = 0, a1 = 0;
#pragma unroll
            for (int j = 0; j < 8; ++j) {
                uint64_t h01, h23;
                lds_v2u64_(ha[par] + j * 16, h01, h23);
                fma2_(a0, wu2[2 * j],     h01);
                fma2_(a1, wu2[2 * j + 1], h23);
            }
            float x0, x1, y0, y1;
            unpack2_(a0, x0, x1);
            unpack2_(a1, y0, y1);
            redU[lc * 8 + s8] = (x0 + x1) + (y0 + y1);
        }

        mbar_wait_par_(mrh_l, parity);               // rhbuf complete
        if (tid == 0) mbar_expect_tx_(mrh_l, 1024);  // re-arm rh (phase t+1)

        // ---- candidate partial: rh[s8*32..+32) . wc ----
        {
            uint64_t c0 = 0, c1 = 0;
#pragma unroll
            for (int j = 0; j < 8; ++j) {
                uint64_t h01, h23;
                lds_v2u64_(ra + j * 16, h01, h23);
                fma2_(c0, wc2[2 * j],     h01);
                fma2_(c1, wc2[2 * j + 1], h23);
            }
            float x0, x1, y0, y1;
            unpack2_(c0, x0, x1);
            unpack2_(c1, y0, y1);
            redB[lc * 8 + s8] = (x0 + x1) + (y0 + y1);
        }
        __syncthreads();   // redB + redU ready; orders tid0's rh re-arm

        // ---- h update (tid<64): u from redU, c from redB ----
        if (tid < 64) {
            float4 u0 = *(const float4*)&redU[tid * 8];
            float4 u1 = *(const float4*)&redU[tid * 8 + 4];
            float su = ((u0.x + u0.y) + (u0.z + u0.w))
                     + ((u1.x + u1.y) + (u1.z + u1.w))
                     + pbuf[cur + 64 + tid];
            float u = fast_sigmoid_(su);

            float4 c0 = *(const float4*)&redB[tid * 8];
            float4 c1 = *(const float4*)&redB[tid * 8 + 4];
            float sc = ((c0.x + c0.y) + (c0.z + c0.w))
                     + ((c1.x + c1.y) + (c1.z + c1.w))
                     + pbuf[cur + 128 + tid];
            float c = fast_tanh_(sc);

            float hn = u * hbuf[par][rank * 64 + tid] + (1.f - u) * c;
            if (t + 1 < T_) {
                const uint32_t dm = npar ? d_h2m1 : d_h2m0;
#pragma unroll
                for (int rk = 0; rk < 4; ++rk)
                    st_async_f32_(h_rem[npar][rk], hn, h_rem[npar][rk] + dm);
            }
            orow[(size_t)t * 256 + rank * 64 + tid] = hn;
        }
        if (tid < 192) pbuf[nxt + tid] = pre_next;
        if (t + 1 < T_) mbar_wait_par_(mh_l, parity);   // hbuf[npar] complete
    }
}

// ---------------------------------------------------------------------------
extern "C" void kernel_launch(void* const* d_in, const int* in_sizes, int n_in,
                              void* d_out, int out_size) {
    const float* x  = (const float*)d_in[0];
    const float* h0 = (const float*)d_in[1];
    const float* Wg = (const float*)d_in[2];
    const float* bg = (const float*)d_in[3];
    const float* Wc = (const float*)d_in[4];
    const float* bc = (const float*)d_in[5];
    float* out = (float*)d_out;

    dim3 g1(12, 512);
    gemm_pre_tf32_kernel<<<g1, 256>>>(x, Wg, bg, Wc, bc);
    gru_rec_kernel<<<128, 512>>>(Wg, Wc, h0, out);
}